// round 11
// baseline (speedup 1.0000x reference)
#include <cuda_runtime.h>

#define NH 8

// Per-head bilinear coefficient tensor (built on device, then copied to constant):
// g_C[h*81 + p*9 + q] = (C0,C1,C2,C3), ev_i = sum_{p,q} g01[p] * C_i[p][q] * g23[q]
__device__ float4 g_C[NH * 81];
__constant__ ulonglong2 c_C[NH * 81];   // .x=(C0,C1) packed, .y=(C2,C3) packed

// ---------------- packed f32x2 helpers ----------------
__device__ __forceinline__ unsigned long long pk2(float lo, float hi) {
    unsigned long long r;
    asm("mov.b64 %0, {%1, %2};" : "=l"(r) : "f"(lo), "f"(hi));
    return r;
}
__device__ __forceinline__ void fma2(unsigned long long& d,
                                     unsigned long long a,
                                     unsigned long long b) {
    asm("fma.rn.f32x2 %0, %1, %2, %0;" : "+l"(d) : "l"(a), "l"(b));
}
__device__ __forceinline__ void unpk2(float& lo, float& hi, unsigned long long v) {
    asm("mov.b64 {%0, %1}, %2;" : "=f"(lo), "=f"(hi) : "l"(v));
}

// ---------------------------------------------------------------------------
// Fused setup (one block per head): evolve U columns, build M_i, contract to C.
// ---------------------------------------------------------------------------
__global__ void build_all(const float* __restrict__ params) {
    int h = blockIdx.x;
    int tid = threadIdx.x;
    __shared__ float sUr[16][16];   // [col][row]
    __shared__ float sUi[16][16];
    __shared__ float sM[4][16][16];

    if (tid < 16) {
        int col = tid;
        float vr[16], vi[16];
#pragma unroll
        for (int i = 0; i < 16; i++) { vr[i] = 0.f; vi[i] = 0.f; }
        vr[col] = 1.f;

        for (int l = 0; l < 2; l++) {
#pragma unroll
            for (int q = 0; q < 4; q++) {
                const float* ph = params + ((h * 2 + l) * 4 + q) * 3;
                const int mask = 8 >> q;
                float c, s;
                __sincosf(0.5f * ph[0], &s, &c);   // RX
#pragma unroll
                for (int i = 0; i < 16; i++) {
                    if (!(i & mask)) {
                        int j = i | mask;
                        float ar0 = vr[i], ai0 = vi[i], ar1 = vr[j], ai1 = vi[j];
                        vr[i] = c * ar0 + s * ai1;
                        vi[i] = c * ai0 - s * ar1;
                        vr[j] = s * ai0 + c * ar1;
                        vi[j] = -s * ar0 + c * ai1;
                    }
                }
                __sincosf(0.5f * ph[1], &s, &c);   // RY
#pragma unroll
                for (int i = 0; i < 16; i++) {
                    if (!(i & mask)) {
                        int j = i | mask;
                        float ar0 = vr[i], ai0 = vi[i], ar1 = vr[j], ai1 = vi[j];
                        vr[i] = c * ar0 - s * ar1;
                        vi[i] = c * ai0 - s * ai1;
                        vr[j] = s * ar0 + c * ar1;
                        vi[j] = s * ai0 + c * ai1;
                    }
                }
                __sincosf(0.5f * ph[2], &s, &c);   // RZ
#pragma unroll
                for (int i = 0; i < 16; i++) {
                    if (!(i & mask)) {
                        int j = i | mask;
                        float ar0 = vr[i], ai0 = vi[i], ar1 = vr[j], ai1 = vi[j];
                        vr[i] = c * ar0 + s * ai0;
                        vi[i] = c * ai0 - s * ar0;
                        vr[j] = c * ar1 - s * ai1;
                        vi[j] = c * ai1 + s * ar1;
                    }
                }
            }
#pragma unroll
            for (int g = 0; g < 4; g++) {          // CNOT ring
                const int cbit = 8 >> g;
                const int tbit = 8 >> ((g + 1) & 3);
#pragma unroll
                for (int i = 0; i < 16; i++) {
                    if ((i & cbit) && !(i & tbit)) {
                        int j = i | tbit;
                        float tr = vr[i]; vr[i] = vr[j]; vr[j] = tr;
                        float ti = vi[i]; vi[i] = vi[j]; vi[j] = ti;
                    }
                }
            }
        }
#pragma unroll
        for (int r = 0; r < 16; r++) {
            sUr[col][r] = vr[r];
            sUi[col][r] = vi[r];
        }
    }
    __syncthreads();

    for (int e = tid; e < 4 * 256; e += blockDim.x) {
        int i = e >> 8;
        int j = (e >> 4) & 15;
        int k = e & 15;
        int zmask = 8 >> i;
        float acc = 0.f;
#pragma unroll
        for (int r = 0; r < 16; r++) {
            float t = sUr[j][r] * sUr[k][r] + sUi[j][r] * sUi[k][r];
            acc += (r & zmask) ? -t : t;
        }
        sM[i][j][k] = acc;
    }
    __syncthreads();

    for (int m = tid; m < 81; m += blockDim.x) {
        int p = m / 9, q = m % 9;
        int mq[4] = { p / 3, p % 3, q / 3, q % 3 };
        float c0 = 0.f, c1 = 0.f, c2 = 0.f, c3 = 0.f;
        for (int t = 0; t < 16; t++) {
            int j = 0, k = 0;
            float sgn = 1.f;
#pragma unroll
            for (int qq = 0; qq < 4; qq++) {
                int b = (t >> (3 - qq)) & 1;
                int jq, kq;
                if (mq[qq] == 0)      { jq = b; kq = b; }
                else if (mq[qq] == 1) { jq = b; kq = b; if (b) sgn = -sgn; }
                else                  { jq = b; kq = 1 - b; }
                j = (j << 1) | jq;
                k = (k << 1) | kq;
            }
            c0 += sgn * sM[0][j][k];
            c1 += sgn * sM[1][j][k];
            c2 += sgn * sM[2][j][k];
            c3 += sgn * sM[3][j][k];
        }
        g_C[h * 81 + m] = make_float4(c0 * 0.0625f, c1 * 0.0625f,
                                      c2 * 0.0625f, c3 * 0.0625f);
    }
}

// ---------------------------------------------------------------------------
// Main: head-parallel. Block = 256 threads = 8 warps; warp w owns head w.
// Block covers 64 tokens; each thread: 2 tokens x 1 head in phase 1.
// Total warps = (ntok/64)*8 = 16384 -> occupancy reg-limited, not work-limited.
// Phase 1: C from __constant__ (uniform per warp), ev -> sEv[64][35]
//          (stride 35: 3 ≡ 35 mod 32, coprime -> conflict-free).
// Phase 2: thread = 1 token x 8 outputs, acc = 4 packed u64.
// ---------------------------------------------------------------------------
#define EVS 35
__global__ __launch_bounds__(256, 3) void qmha_main(
    const float* __restrict__ x,
    const float* __restrict__ W,      // [32][32] row-major
    const float* __restrict__ bvec,   // [32]
    float* __restrict__ out,
    int ntok)
{
    __shared__ float sEv[64 * EVS];
    __shared__ __align__(16) float sWt[32 * 32];  // sWt[k*32+j] = W[j*32+k]
    __shared__ float sb[32];

    int tid = threadIdx.x;
    int wid = tid >> 5;      // warp id = head id
    int lane = tid & 31;

    for (int i = tid; i < 1024; i += 256) {
        int k = i >> 5, j = i & 31;
        sWt[k * 32 + j] = W[j * 32 + k];
    }
    if (tid < 32) sb[tid] = bvec[tid];

    int base = blockIdx.x * 64;
    int h = wid;
    int tA = base + lane;          // token A
    int tB = base + 32 + lane;     // token B

    const float4 aA = reinterpret_cast<const float4*>(
        x + (size_t)(tA < ntok ? tA : 0) * 32)[h];
    const float4 aB = reinterpret_cast<const float4*>(
        x + (size_t)(tB < ntok ? tB : 0) * 32)[h];

    // ---- Phase 1: bilinear form for (2 tokens, 1 head) ----
    float cA0, sA0, cA1, sA1, cA2, sA2, cA3, sA3;
    float cB0, sB0, cB1, sB1, cB2, sB2, cB3, sB3;
    __sincosf(aA.x, &sA0, &cA0);
    __sincosf(aA.y, &sA1, &cA1);
    __sincosf(aA.z, &sA2, &cA2);
    __sincosf(aA.w, &sA3, &cA3);
    __sincosf(aB.x, &sB0, &cB0);
    __sincosf(aB.y, &sB1, &cB1);
    __sincosf(aB.z, &sB2, &cB2);
    __sincosf(aB.w, &sB3, &cB3);

    const unsigned long long ONE2 = pk2(1.f, 1.f);

    // g23 duplicated pairs; q=0 entry is the constant 1 (not stored)
    unsigned long long gA23d[9], gB23d[9];
    {
        float gA23[9] = { 1.f, cA3, sA3, cA2, cA2*cA3, cA2*sA3, sA2, sA2*cA3, sA2*sA3 };
        float gB23[9] = { 1.f, cB3, sB3, cB2, cB2*cB3, cB2*sB3, sB2, sB2*cB3, sB2*sB3 };
        gA23d[0] = ONE2; gB23d[0] = ONE2;
#pragma unroll
        for (int q = 1; q < 9; q++) {
            gA23d[q] = pk2(gA23[q], gA23[q]);
            gB23d[q] = pk2(gB23[q], gB23[q]);
        }
    }

    float uA[3] = { 1.f, cA0, sA0 }, vA[3] = { 1.f, cA1, sA1 };
    float uB[3] = { 1.f, cB0, sB0 }, vB[3] = { 1.f, cB1, sB1 };

    unsigned long long evA01 = 0ULL, evA23 = 0ULL;
    unsigned long long evB01 = 0ULL, evB23 = 0ULL;
#pragma unroll
    for (int p = 0; p < 9; p++) {
        unsigned long long tA01 = 0ULL, tA23 = 0ULL;
        unsigned long long tB01 = 0ULL, tB23 = 0ULL;
#pragma unroll
        for (int q = 0; q < 9; q++) {
            ulonglong2 cc = c_C[h * 81 + p * 9 + q];   // LDC.128, warp-uniform
            fma2(tA01, cc.x, gA23d[q]);
            fma2(tA23, cc.y, gA23d[q]);
            fma2(tB01, cc.x, gB23d[q]);
            fma2(tB23, cc.y, gB23d[q]);
        }
        float gA = uA[p / 3] * vA[p % 3];
        float gB = uB[p / 3] * vB[p % 3];
        unsigned long long gpA = pk2(gA, gA);
        unsigned long long gpB = pk2(gB, gB);
        fma2(evA01, gpA, tA01);
        fma2(evA23, gpA, tA23);
        fma2(evB01, gpB, tB01);
        fma2(evB23, gpB, tB23);
    }

    {
        float e0, e1, e2, e3;
        unpk2(e0, e1, evA01); unpk2(e2, e3, evA23);
        float* d = &sEv[lane * EVS + h * 4];
        d[0] = e0; d[1] = e1; d[2] = e2; d[3] = e3;
        unpk2(e0, e1, evB01); unpk2(e2, e3, evB23);
        float* d2 = &sEv[(32 + lane) * EVS + h * 4];
        d2[0] = e0; d2[1] = e1; d2[2] = e2; d2[3] = e3;
    }

    __syncthreads();

    // ---- Phase 2: out[64][32] = ev[64][32] @ sWt[32][32] + b ----
    // thread = 1 token x 8 outputs; jg warp-uniform (tid>>6).
    int jg = tid >> 6;       // 0..3, uniform within warp
    int tok = tid & 63;      // 0..63; warp lanes hold consecutive tokens

    unsigned long long acc[4];
#pragma unroll
    for (int c = 0; c < 4; c++)
        acc[c] = pk2(sb[jg * 8 + 2 * c], sb[jg * 8 + 2 * c + 1]);

#pragma unroll
    for (int k = 0; k < 32; k++) {
        const ulonglong2* w2 =
            reinterpret_cast<const ulonglong2*>(sWt + k * 32 + jg * 8);
        ulonglong2 wa = w2[0];   // outputs jg*8+0..3
        ulonglong2 wb = w2[1];   // outputs jg*8+4..7
        float e = sEv[tok * EVS + k];   // bank (3*tok + k) % 32: conflict-free
        unsigned long long ed = pk2(e, e);
        fma2(acc[0], ed, wa.x);
        fma2(acc[1], ed, wa.y);
        fma2(acc[2], ed, wb.x);
        fma2(acc[3], ed, wb.y);
    }

    int t = base + tok;
    if (t < ntok) {
        float4* o = reinterpret_cast<float4*>(out + (size_t)t * 32 + jg * 8);
        float a0, a1, a2, a3;
        unpk2(a0, a1, acc[0]);
        unpk2(a2, a3, acc[1]);
        o[0] = make_float4(a0, a1, a2, a3);
        unpk2(a0, a1, acc[2]);
        unpk2(a2, a3, acc[3]);
        o[1] = make_float4(a0, a1, a2, a3);
    }
}

extern "C" void kernel_launch(void* const* d_in, const int* in_sizes, int n_in,
                              void* d_out, int out_size) {
    const float* x      = (const float*)d_in[0];  // [B,S,32]
    const float* params = (const float*)d_in[1];  // [8,2,4,3]
    const float* W      = (const float*)d_in[2];  // [32,32]
    const float* b      = (const float*)d_in[3];  // [32]
    float* out = (float*)d_out;

    int ntok = in_sizes[0] / 32;

    build_all<<<NH, 128>>>(params);

    // D2D memcpy into the constant bank (proven capturable in round 7).
    void* gC_ptr = nullptr;
    void* cC_ptr = nullptr;
    cudaGetSymbolAddress(&gC_ptr, g_C);
    cudaGetSymbolAddress(&cC_ptr, c_C);
    cudaMemcpyAsync(cC_ptr, gC_ptr, sizeof(float4) * NH * 81,
                    cudaMemcpyDeviceToDevice, 0);

    int blocks = (ntok + 63) / 64;
    qmha_main<<<blocks, 256>>>(x, W, b, out, ntok);
}

// round 13
// speedup vs baseline: 2.0279x; 2.0279x over previous
#include <cuda_runtime.h>

#define NH 8

// Per-head bilinear coefficient tensor (built on device, then copied to constant):
// g_C[h*81 + p*9 + q] = (C0,C1,C2,C3), ev_i = sum_{p,q} g01[p] * C_i[p][q] * g23[q]
__device__ float4 g_C[NH * 81];
__constant__ ulonglong2 c_C[NH * 81];   // .x=(C0,C1) packed, .y=(C2,C3) packed

// ---------------- packed f32x2 helpers ----------------
__device__ __forceinline__ unsigned long long pk2(float lo, float hi) {
    unsigned long long r;
    asm("mov.b64 %0, {%1, %2};" : "=l"(r) : "f"(lo), "f"(hi));
    return r;
}
__device__ __forceinline__ void fma2(unsigned long long& d,
                                     unsigned long long a,
                                     unsigned long long b) {
    asm("fma.rn.f32x2 %0, %1, %2, %0;" : "+l"(d) : "l"(a), "l"(b));
}
__device__ __forceinline__ void unpk2(float& lo, float& hi, unsigned long long v) {
    asm("mov.b64 {%0, %1}, %2;" : "=f"(lo), "=f"(hi) : "l"(v));
}

// ---------------------------------------------------------------------------
// Fused setup (one block per head): evolve U columns, build M_i, contract to C.
// ---------------------------------------------------------------------------
__global__ void build_all(const float* __restrict__ params) {
    int h = blockIdx.x;
    int tid = threadIdx.x;
    __shared__ float sUr[16][16];   // [col][row]
    __shared__ float sUi[16][16];
    __shared__ float sM[4][16][16];

    if (tid < 16) {
        int col = tid;
        float vr[16], vi[16];
#pragma unroll
        for (int i = 0; i < 16; i++) { vr[i] = 0.f; vi[i] = 0.f; }
        vr[col] = 1.f;

        for (int l = 0; l < 2; l++) {
#pragma unroll
            for (int q = 0; q < 4; q++) {
                const float* ph = params + ((h * 2 + l) * 4 + q) * 3;
                const int mask = 8 >> q;
                float c, s;
                __sincosf(0.5f * ph[0], &s, &c);   // RX
#pragma unroll
                for (int i = 0; i < 16; i++) {
                    if (!(i & mask)) {
                        int j = i | mask;
                        float ar0 = vr[i], ai0 = vi[i], ar1 = vr[j], ai1 = vi[j];
                        vr[i] = c * ar0 + s * ai1;
                        vi[i] = c * ai0 - s * ar1;
                        vr[j] = s * ai0 + c * ar1;
                        vi[j] = -s * ar0 + c * ai1;
                    }
                }
                __sincosf(0.5f * ph[1], &s, &c);   // RY
#pragma unroll
                for (int i = 0; i < 16; i++) {
                    if (!(i & mask)) {
                        int j = i | mask;
                        float ar0 = vr[i], ai0 = vi[i], ar1 = vr[j], ai1 = vi[j];
                        vr[i] = c * ar0 - s * ar1;
                        vi[i] = c * ai0 - s * ai1;
                        vr[j] = s * ar0 + c * ar1;
                        vi[j] = s * ai0 + c * ai1;
                    }
                }
                __sincosf(0.5f * ph[2], &s, &c);   // RZ
#pragma unroll
                for (int i = 0; i < 16; i++) {
                    if (!(i & mask)) {
                        int j = i | mask;
                        float ar0 = vr[i], ai0 = vi[i], ar1 = vr[j], ai1 = vi[j];
                        vr[i] = c * ar0 + s * ai0;
                        vi[i] = c * ai0 - s * ar0;
                        vr[j] = c * ar1 - s * ai1;
                        vi[j] = c * ai1 + s * ar1;
                    }
                }
            }
#pragma unroll
            for (int g = 0; g < 4; g++) {          // CNOT ring
                const int cbit = 8 >> g;
                const int tbit = 8 >> ((g + 1) & 3);
#pragma unroll
                for (int i = 0; i < 16; i++) {
                    if ((i & cbit) && !(i & tbit)) {
                        int j = i | tbit;
                        float tr = vr[i]; vr[i] = vr[j]; vr[j] = tr;
                        float ti = vi[i]; vi[i] = vi[j]; vi[j] = ti;
                    }
                }
            }
        }
#pragma unroll
        for (int r = 0; r < 16; r++) {
            sUr[col][r] = vr[r];
            sUi[col][r] = vi[r];
        }
    }
    __syncthreads();

    for (int e = tid; e < 4 * 256; e += blockDim.x) {
        int i = e >> 8;
        int j = (e >> 4) & 15;
        int k = e & 15;
        int zmask = 8 >> i;
        float acc = 0.f;
#pragma unroll
        for (int r = 0; r < 16; r++) {
            float t = sUr[j][r] * sUr[k][r] + sUi[j][r] * sUi[k][r];
            acc += (r & zmask) ? -t : t;
        }
        sM[i][j][k] = acc;
    }
    __syncthreads();

    for (int m = tid; m < 81; m += blockDim.x) {
        int p = m / 9, q = m % 9;
        int mq[4] = { p / 3, p % 3, q / 3, q % 3 };
        float c0 = 0.f, c1 = 0.f, c2 = 0.f, c3 = 0.f;
        for (int t = 0; t < 16; t++) {
            int j = 0, k = 0;
            float sgn = 1.f;
#pragma unroll
            for (int qq = 0; qq < 4; qq++) {
                int b = (t >> (3 - qq)) & 1;
                int jq, kq;
                if (mq[qq] == 0)      { jq = b; kq = b; }
                else if (mq[qq] == 1) { jq = b; kq = b; if (b) sgn = -sgn; }
                else                  { jq = b; kq = 1 - b; }
                j = (j << 1) | jq;
                k = (k << 1) | kq;
            }
            c0 += sgn * sM[0][j][k];
            c1 += sgn * sM[1][j][k];
            c2 += sgn * sM[2][j][k];
            c3 += sgn * sM[3][j][k];
        }
        g_C[h * 81 + m] = make_float4(c0 * 0.0625f, c1 * 0.0625f,
                                      c2 * 0.0625f, c3 * 0.0625f);
    }
}

// ---------------------------------------------------------------------------
// Main: block = 128 threads, 128 tokens. Grid = ntok/128 = 1024 blocks
// -> 4096 warps (~28/SM resident): twice r7's warp count.
// Phase 1: 1 token/thread, C from __constant__ with COMPILE-TIME indices
//          (h,p,q all unrolled -> immediate-offset uniform loads, rt=1 port,
//          zero l1tex crossbar traffic). ev -> smem tile [128][33].
// Phase 2: block GEMM out = ev @ Wt + b; thread = 4 tokens x 8 outputs.
// ---------------------------------------------------------------------------
__global__ __launch_bounds__(128, 7) void qmha_main(
    const float* __restrict__ x,
    const float* __restrict__ W,      // [32][32] row-major
    const float* __restrict__ bvec,   // [32]
    float* __restrict__ out,
    int ntok)
{
    __shared__ float sEv[128 * 33];
    __shared__ __align__(16) float sWt[32 * 32];      // sWt[k*32+j] = W[j*32+k]
    __shared__ float sb[32];

    int tid = threadIdx.x;
    for (int i = tid; i < 1024; i += 128) {
        int k = i >> 5, j = i & 31;
        sWt[k * 32 + j] = W[j * 32 + k];
    }
    if (tid < 32) sb[tid] = bvec[tid];

    int base = blockIdx.x * 128;
    int t = base + tid;
    const float4* xt = reinterpret_cast<const float4*>(
        x + (size_t)(t < ntok ? t : 0) * 32);

    // ---- Phase 1: one token per thread, all heads (compile-time h) ----
#pragma unroll
    for (int h = 0; h < NH; h++) {
        float4 ang = xt[h];
        float c0, s0, c1, s1, c2, s2, c3, s3;
        __sincosf(ang.x, &s0, &c0);
        __sincosf(ang.y, &s1, &c1);
        __sincosf(ang.z, &s2, &c2);
        __sincosf(ang.w, &s3, &c3);

        // g01[p] rebuilt on the fly: u[p/3] * v[p%3]
        float u[3] = { 1.f, c0, s0 }, v[3] = { 1.f, c1, s1 };

        unsigned long long g23d[9];
        {
            float g23[9] = { 1.f, c3, s3, c2, c2*c3, c2*s3, s2, s2*c3, s2*s3 };
#pragma unroll
            for (int q = 0; q < 9; q++) g23d[q] = pk2(g23[q], g23[q]);
        }

        unsigned long long ev01 = 0ULL, ev23 = 0ULL;
#pragma unroll
        for (int p = 0; p < 9; p++) {
            unsigned long long t01 = 0ULL, t23 = 0ULL;
#pragma unroll
            for (int q = 0; q < 9; q++) {
                // h, p, q are all compile-time constants here -> immediate
                // offset constant loads (uniform path).
                ulonglong2 cc = c_C[h * 81 + p * 9 + q];
                fma2(t01, cc.x, g23d[q]);
                fma2(t23, cc.y, g23d[q]);
            }
            float g = u[p / 3] * v[p % 3];
            unsigned long long gp = pk2(g, g);
            fma2(ev01, gp, t01);
            fma2(ev23, gp, t23);
        }

        float e0, e1, e2, e3;
        unpk2(e0, e1, ev01);
        unpk2(e2, e3, ev23);
        sEv[tid * 33 + h * 4 + 0] = e0;
        sEv[tid * 33 + h * 4 + 1] = e1;
        sEv[tid * 33 + h * 4 + 2] = e2;
        sEv[tid * 33 + h * 4 + 3] = e3;
    }

    __syncthreads();

    // ---- Phase 2: out[128][32] = ev[128][32] @ sWt[32][32] + b ----
    int jg = tid & 3;        // output group of 8: columns jg*8 .. jg*8+7
    int tg = tid >> 2;       // token sub-index (0..31); tokens tg + 32*m

    unsigned long long acc[4][4];
#pragma unroll
    for (int m = 0; m < 4; m++)
#pragma unroll
        for (int c = 0; c < 4; c++)
            acc[m][c] = pk2(sb[jg * 8 + 2 * c], sb[jg * 8 + 2 * c + 1]);

#pragma unroll
    for (int k = 0; k < 32; k++) {
        const ulonglong2* w2 =
            reinterpret_cast<const ulonglong2*>(sWt + k * 32 + jg * 8);
        ulonglong2 wa = w2[0];   // outputs jg*8+0..3
        ulonglong2 wb = w2[1];   // outputs jg*8+4..7
#pragma unroll
        for (int m = 0; m < 4; m++) {
            float e = sEv[(tg + 32 * m) * 33 + k];  // bank (tg+k)%32, bcast x4
            unsigned long long ed = pk2(e, e);
            fma2(acc[m][0], ed, wa.x);
            fma2(acc[m][1], ed, wa.y);
            fma2(acc[m][2], ed, wb.x);
            fma2(acc[m][3], ed, wb.y);
        }
    }

#pragma unroll
    for (int m = 0; m < 4; m++) {
        int to = base + tg + 32 * m;
        if (to < ntok) {
            float4* o = reinterpret_cast<float4*>(out + (size_t)to * 32 + jg * 8);
            float a0, a1, a2, a3;
            unpk2(a0, a1, acc[m][0]);
            unpk2(a2, a3, acc[m][1]);
            o[0] = make_float4(a0, a1, a2, a3);
            unpk2(a0, a1, acc[m][2]);
            unpk2(a2, a3, acc[m][3]);
            o[1] = make_float4(a0, a1, a2, a3);
        }
    }
}

extern "C" void kernel_launch(void* const* d_in, const int* in_sizes, int n_in,
                              void* d_out, int out_size) {
    const float* x      = (const float*)d_in[0];  // [B,S,32]
    const float* params = (const float*)d_in[1];  // [8,2,4,3]
    const float* W      = (const float*)d_in[2];  // [32,32]
    const float* b      = (const float*)d_in[3];  // [32]
    float* out = (float*)d_out;

    int ntok = in_sizes[0] / 32;

    build_all<<<NH, 128>>>(params);

    // D2D memcpy into the constant bank (proven capturable in round 7).
    void* gC_ptr = nullptr;
    void* cC_ptr = nullptr;
    cudaGetSymbolAddress(&gC_ptr, g_C);
    cudaGetSymbolAddress(&cC_ptr, c_C);
    cudaMemcpyAsync(cC_ptr, gC_ptr, sizeof(float4) * NH * 81,
                    cudaMemcpyDeviceToDevice, 0);

    int blocks = (ntok + 127) / 128;
    qmha_main<<<blocks, 128>>>(x, W, b, out, ntok);
}

// round 14
// speedup vs baseline: 2.0784x; 1.0249x over previous
#include <cuda_runtime.h>

#define NH 8

// Per-head bilinear coefficient tensor (built on device, then copied to constant):
// g_C[h*81 + p*9 + q] = (C0,C1,C2,C3), ev_i = sum_{p,q} g01[p] * C_i[p][q] * g23[q]
__device__ float4 g_C[NH * 81];
__constant__ ulonglong2 c_C[NH * 81];   // .x=(C0,C1) packed, .y=(C2,C3) packed

// ---------------- packed f32x2 helpers ----------------
__device__ __forceinline__ unsigned long long pk2(float lo, float hi) {
    unsigned long long r;
    asm("mov.b64 %0, {%1, %2};" : "=l"(r) : "f"(lo), "f"(hi));
    return r;
}
__device__ __forceinline__ void fma2(unsigned long long& d,
                                     unsigned long long a,
                                     unsigned long long b) {
    asm("fma.rn.f32x2 %0, %1, %2, %0;" : "+l"(d) : "l"(a), "l"(b));
}
__device__ __forceinline__ void unpk2(float& lo, float& hi, unsigned long long v) {
    asm("mov.b64 {%0, %1}, %2;" : "=f"(lo), "=f"(hi) : "l"(v));
}

// ---------------------------------------------------------------------------
// Fused setup (one block per head): evolve U columns, build M_i, contract to C.
// ---------------------------------------------------------------------------
__global__ void build_all(const float* __restrict__ params) {
    int h = blockIdx.x;
    int tid = threadIdx.x;
    __shared__ float sUr[16][16];   // [col][row]
    __shared__ float sUi[16][16];
    __shared__ float sM[4][16][16];

    if (tid < 16) {
        int col = tid;
        float vr[16], vi[16];
#pragma unroll
        for (int i = 0; i < 16; i++) { vr[i] = 0.f; vi[i] = 0.f; }
        vr[col] = 1.f;

        for (int l = 0; l < 2; l++) {
#pragma unroll
            for (int q = 0; q < 4; q++) {
                const float* ph = params + ((h * 2 + l) * 4 + q) * 3;
                const int mask = 8 >> q;
                float c, s;
                __sincosf(0.5f * ph[0], &s, &c);   // RX
#pragma unroll
                for (int i = 0; i < 16; i++) {
                    if (!(i & mask)) {
                        int j = i | mask;
                        float ar0 = vr[i], ai0 = vi[i], ar1 = vr[j], ai1 = vi[j];
                        vr[i] = c * ar0 + s * ai1;
                        vi[i] = c * ai0 - s * ar1;
                        vr[j] = s * ai0 + c * ar1;
                        vi[j] = -s * ar0 + c * ai1;
                    }
                }
                __sincosf(0.5f * ph[1], &s, &c);   // RY
#pragma unroll
                for (int i = 0; i < 16; i++) {
                    if (!(i & mask)) {
                        int j = i | mask;
                        float ar0 = vr[i], ai0 = vi[i], ar1 = vr[j], ai1 = vi[j];
                        vr[i] = c * ar0 - s * ar1;
                        vi[i] = c * ai0 - s * ai1;
                        vr[j] = s * ar0 + c * ar1;
                        vi[j] = s * ai0 + c * ai1;
                    }
                }
                __sincosf(0.5f * ph[2], &s, &c);   // RZ
#pragma unroll
                for (int i = 0; i < 16; i++) {
                    if (!(i & mask)) {
                        int j = i | mask;
                        float ar0 = vr[i], ai0 = vi[i], ar1 = vr[j], ai1 = vi[j];
                        vr[i] = c * ar0 + s * ai0;
                        vi[i] = c * ai0 - s * ar0;
                        vr[j] = c * ar1 - s * ai1;
                        vi[j] = c * ai1 + s * ar1;
                    }
                }
            }
#pragma unroll
            for (int g = 0; g < 4; g++) {          // CNOT ring
                const int cbit = 8 >> g;
                const int tbit = 8 >> ((g + 1) & 3);
#pragma unroll
                for (int i = 0; i < 16; i++) {
                    if ((i & cbit) && !(i & tbit)) {
                        int j = i | tbit;
                        float tr = vr[i]; vr[i] = vr[j]; vr[j] = tr;
                        float ti = vi[i]; vi[i] = vi[j]; vi[j] = ti;
                    }
                }
            }
        }
#pragma unroll
        for (int r = 0; r < 16; r++) {
            sUr[col][r] = vr[r];
            sUi[col][r] = vi[r];
        }
    }
    __syncthreads();

    for (int e = tid; e < 4 * 256; e += blockDim.x) {
        int i = e >> 8;
        int j = (e >> 4) & 15;
        int k = e & 15;
        int zmask = 8 >> i;
        float acc = 0.f;
#pragma unroll
        for (int r = 0; r < 16; r++) {
            float t = sUr[j][r] * sUr[k][r] + sUi[j][r] * sUi[k][r];
            acc += (r & zmask) ? -t : t;
        }
        sM[i][j][k] = acc;
    }
    __syncthreads();

    for (int m = tid; m < 81; m += blockDim.x) {
        int p = m / 9, q = m % 9;
        int mq[4] = { p / 3, p % 3, q / 3, q % 3 };
        float c0 = 0.f, c1 = 0.f, c2 = 0.f, c3 = 0.f;
        for (int t = 0; t < 16; t++) {
            int j = 0, k = 0;
            float sgn = 1.f;
#pragma unroll
            for (int qq = 0; qq < 4; qq++) {
                int b = (t >> (3 - qq)) & 1;
                int jq, kq;
                if (mq[qq] == 0)      { jq = b; kq = b; }
                else if (mq[qq] == 1) { jq = b; kq = b; if (b) sgn = -sgn; }
                else                  { jq = b; kq = 1 - b; }
                j = (j << 1) | jq;
                k = (k << 1) | kq;
            }
            c0 += sgn * sM[0][j][k];
            c1 += sgn * sM[1][j][k];
            c2 += sgn * sM[2][j][k];
            c3 += sgn * sM[3][j][k];
        }
        g_C[h * 81 + m] = make_float4(c0 * 0.0625f, c1 * 0.0625f,
                                      c2 * 0.0625f, c3 * 0.0625f);
    }
}

// ---------------------------------------------------------------------------
// Main: block = 128 threads, 128 tokens, grid = 1024 (max warp residency).
// Phase 1: 1 token/thread, C split across ports by p-parity:
//   even p -> __constant__ (LDC.128, immediate offsets)
//   odd  p -> smem mirror  (LDS.128, uniform broadcast = 1 wavefront)
// halving the constant-port stream that bound round 13.
// Phase 2: block GEMM out = ev @ Wt + b; thread = 4 tokens x 8 outputs.
// ---------------------------------------------------------------------------
__global__ __launch_bounds__(128, 6) void qmha_main(
    const float* __restrict__ x,
    const float* __restrict__ W,      // [32][32] row-major
    const float* __restrict__ bvec,   // [32]
    float* __restrict__ out,
    int ntok)
{
    __shared__ float sEv[128 * 33];
    __shared__ __align__(16) ulonglong2 sC[NH * 81];  // smem mirror of C
    __shared__ __align__(16) float sWt[32 * 32];      // sWt[k*32+j] = W[j*32+k]
    __shared__ float sb[32];

    int tid = threadIdx.x;
    {
        const float4* src = reinterpret_cast<const float4*>(g_C);
        float4* dst = reinterpret_cast<float4*>(sC);
        for (int i = tid; i < NH * 81; i += 128) dst[i] = src[i];
    }
    for (int i = tid; i < 1024; i += 128) {
        int k = i >> 5, j = i & 31;
        sWt[k * 32 + j] = W[j * 32 + k];
    }
    if (tid < 32) sb[tid] = bvec[tid];
    __syncthreads();

    int base = blockIdx.x * 128;
    int t = base + tid;
    const float4* xt = reinterpret_cast<const float4*>(
        x + (size_t)(t < ntok ? t : 0) * 32);

    // ---- Phase 1: one token per thread, all heads (compile-time h) ----
#pragma unroll
    for (int h = 0; h < NH; h++) {
        float4 ang = xt[h];
        float c0, s0, c1, s1, c2, s2, c3, s3;
        __sincosf(ang.x, &s0, &c0);
        __sincosf(ang.y, &s1, &c1);
        __sincosf(ang.z, &s2, &c2);
        __sincosf(ang.w, &s3, &c3);

        // g01[p] rebuilt on the fly: u[p/3] * v[p%3]
        float u[3] = { 1.f, c0, s0 }, v[3] = { 1.f, c1, s1 };

        unsigned long long g23d[9];
        {
            float g23[9] = { 1.f, c3, s3, c2, c2*c3, c2*s3, s2, s2*c3, s2*s3 };
#pragma unroll
            for (int q = 0; q < 9; q++) g23d[q] = pk2(g23[q], g23[q]);
        }

        unsigned long long ev01 = 0ULL, ev23 = 0ULL;
#pragma unroll
        for (int p = 0; p < 9; p++) {
            unsigned long long t01 = 0ULL, t23 = 0ULL;
#pragma unroll
            for (int q = 0; q < 9; q++) {
                // h, p, q all compile-time -> immediate-offset loads.
                // Port split by p-parity: even p on constant port,
                // odd p on shared crossbar (uniform broadcast).
                ulonglong2 cc;
                if ((p & 1) == 0) cc = c_C[h * 81 + p * 9 + q];
                else              cc = sC[h * 81 + p * 9 + q];
                fma2(t01, cc.x, g23d[q]);
                fma2(t23, cc.y, g23d[q]);
            }
            float g = u[p / 3] * v[p % 3];
            unsigned long long gp = pk2(g, g);
            fma2(ev01, gp, t01);
            fma2(ev23, gp, t23);
        }

        float e0, e1, e2, e3;
        unpk2(e0, e1, ev01);
        unpk2(e2, e3, ev23);
        sEv[tid * 33 + h * 4 + 0] = e0;
        sEv[tid * 33 + h * 4 + 1] = e1;
        sEv[tid * 33 + h * 4 + 2] = e2;
        sEv[tid * 33 + h * 4 + 3] = e3;
    }

    __syncthreads();

    // ---- Phase 2: out[128][32] = ev[128][32] @ sWt[32][32] + b ----
    int jg = tid & 3;        // output group of 8: columns jg*8 .. jg*8+7
    int tg = tid >> 2;       // token sub-index (0..31); tokens tg + 32*m

    unsigned long long acc[4][4];
#pragma unroll
    for (int m = 0; m < 4; m++)
#pragma unroll
        for (int c = 0; c < 4; c++)
            acc[m][c] = pk2(sb[jg * 8 + 2 * c], sb[jg * 8 + 2 * c + 1]);

#pragma unroll
    for (int k = 0; k < 32; k++) {
        const ulonglong2* w2 =
            reinterpret_cast<const ulonglong2*>(sWt + k * 32 + jg * 8);
        ulonglong2 wa = w2[0];   // outputs jg*8+0..3
        ulonglong2 wb = w2[1];   // outputs jg*8+4..7
#pragma unroll
        for (int m = 0; m < 4; m++) {
            float e = sEv[(tg + 32 * m) * 33 + k];  // bank (tg+k)%32, bcast x4
            unsigned long long ed = pk2(e, e);
            fma2(acc[m][0], ed, wa.x);
            fma2(acc[m][1], ed, wa.y);
            fma2(acc[m][2], ed, wb.x);
            fma2(acc[m][3], ed, wb.y);
        }
    }

#pragma unroll
    for (int m = 0; m < 4; m++) {
        int to = base + tg + 32 * m;
        if (to < ntok) {
            float4* o = reinterpret_cast<float4*>(out + (size_t)to * 32 + jg * 8);
            float a0, a1, a2, a3;
            unpk2(a0, a1, acc[m][0]);
            unpk2(a2, a3, acc[m][1]);
            o[0] = make_float4(a0, a1, a2, a3);
            unpk2(a0, a1, acc[m][2]);
            unpk2(a2, a3, acc[m][3]);
            o[1] = make_float4(a0, a1, a2, a3);
        }
    }
}

extern "C" void kernel_launch(void* const* d_in, const int* in_sizes, int n_in,
                              void* d_out, int out_size) {
    const float* x      = (const float*)d_in[0];  // [B,S,32]
    const float* params = (const float*)d_in[1];  // [8,2,4,3]
    const float* W      = (const float*)d_in[2];  // [32,32]
    const float* b      = (const float*)d_in[3];  // [32]
    float* out = (float*)d_out;

    int ntok = in_sizes[0] / 32;

    build_all<<<NH, 128>>>(params);

    // D2D memcpy into the constant bank (proven capturable).
    void* gC_ptr = nullptr;
    void* cC_ptr = nullptr;
    cudaGetSymbolAddress(&gC_ptr, g_C);
    cudaGetSymbolAddress(&cC_ptr, c_C);
    cudaMemcpyAsync(cC_ptr, gC_ptr, sizeof(float4) * NH * 81,
                    cudaMemcpyDeviceToDevice, 0);

    int blocks = (ntok + 127) / 128;
    qmha_main<<<blocks, 128>>>(x, W, b, out, ntok);
}

// round 15
// speedup vs baseline: 2.1363x; 1.0279x over previous
#include <cuda_runtime.h>

#define NH 8

// Per-head bilinear coefficient tensor (built on device, then copied to constant):
// g_C[h*81 + p*9 + q] = (C0,C1,C2,C3), ev_i = sum_{p,q} g01[p] * C_i[p][q] * g23[q]
__device__ float4 g_C[NH * 81];
__constant__ ulonglong2 c_C[NH * 81];   // .x=(C0,C1) packed, .y=(C2,C3) packed

// ---------------- packed f32x2 helpers ----------------
__device__ __forceinline__ unsigned long long pk2(float lo, float hi) {
    unsigned long long r;
    asm("mov.b64 %0, {%1, %2};" : "=l"(r) : "f"(lo), "f"(hi));
    return r;
}
__device__ __forceinline__ void fma2(unsigned long long& d,
                                     unsigned long long a,
                                     unsigned long long b) {
    asm("fma.rn.f32x2 %0, %1, %2, %0;" : "+l"(d) : "l"(a), "l"(b));
}
__device__ __forceinline__ void unpk2(float& lo, float& hi, unsigned long long v) {
    asm("mov.b64 {%0, %1}, %2;" : "=f"(lo), "=f"(hi) : "l"(v));
}

// ---------------------------------------------------------------------------
// Fused setup (one block per head): evolve U columns, build M_i, contract to C.
// ---------------------------------------------------------------------------
__global__ void build_all(const float* __restrict__ params) {
    int h = blockIdx.x;
    int tid = threadIdx.x;
    __shared__ float sUr[16][16];   // [col][row]
    __shared__ float sUi[16][16];
    __shared__ float sM[4][16][16];

    if (tid < 16) {
        int col = tid;
        float vr[16], vi[16];
#pragma unroll
        for (int i = 0; i < 16; i++) { vr[i] = 0.f; vi[i] = 0.f; }
        vr[col] = 1.f;

        for (int l = 0; l < 2; l++) {
#pragma unroll
            for (int q = 0; q < 4; q++) {
                const float* ph = params + ((h * 2 + l) * 4 + q) * 3;
                const int mask = 8 >> q;
                float c, s;
                __sincosf(0.5f * ph[0], &s, &c);   // RX
#pragma unroll
                for (int i = 0; i < 16; i++) {
                    if (!(i & mask)) {
                        int j = i | mask;
                        float ar0 = vr[i], ai0 = vi[i], ar1 = vr[j], ai1 = vi[j];
                        vr[i] = c * ar0 + s * ai1;
                        vi[i] = c * ai0 - s * ar1;
                        vr[j] = s * ai0 + c * ar1;
                        vi[j] = -s * ar0 + c * ai1;
                    }
                }
                __sincosf(0.5f * ph[1], &s, &c);   // RY
#pragma unroll
                for (int i = 0; i < 16; i++) {
                    if (!(i & mask)) {
                        int j = i | mask;
                        float ar0 = vr[i], ai0 = vi[i], ar1 = vr[j], ai1 = vi[j];
                        vr[i] = c * ar0 - s * ar1;
                        vi[i] = c * ai0 - s * ai1;
                        vr[j] = s * ar0 + c * ar1;
                        vi[j] = s * ai0 + c * ai1;
                    }
                }
                __sincosf(0.5f * ph[2], &s, &c);   // RZ
#pragma unroll
                for (int i = 0; i < 16; i++) {
                    if (!(i & mask)) {
                        int j = i | mask;
                        float ar0 = vr[i], ai0 = vi[i], ar1 = vr[j], ai1 = vi[j];
                        vr[i] = c * ar0 + s * ai0;
                        vi[i] = c * ai0 - s * ar0;
                        vr[j] = c * ar1 - s * ai1;
                        vi[j] = c * ai1 + s * ar1;
                    }
                }
            }
#pragma unroll
            for (int g = 0; g < 4; g++) {          // CNOT ring
                const int cbit = 8 >> g;
                const int tbit = 8 >> ((g + 1) & 3);
#pragma unroll
                for (int i = 0; i < 16; i++) {
                    if ((i & cbit) && !(i & tbit)) {
                        int j = i | tbit;
                        float tr = vr[i]; vr[i] = vr[j]; vr[j] = tr;
                        float ti = vi[i]; vi[i] = vi[j]; vi[j] = ti;
                    }
                }
            }
        }
#pragma unroll
        for (int r = 0; r < 16; r++) {
            sUr[col][r] = vr[r];
            sUi[col][r] = vi[r];
        }
    }
    __syncthreads();

    for (int e = tid; e < 4 * 256; e += blockDim.x) {
        int i = e >> 8;
        int j = (e >> 4) & 15;
        int k = e & 15;
        int zmask = 8 >> i;
        float acc = 0.f;
#pragma unroll
        for (int r = 0; r < 16; r++) {
            float t = sUr[j][r] * sUr[k][r] + sUi[j][r] * sUi[k][r];
            acc += (r & zmask) ? -t : t;
        }
        sM[i][j][k] = acc;
    }
    __syncthreads();

    for (int m = tid; m < 81; m += blockDim.x) {
        int p = m / 9, q = m % 9;
        int mq[4] = { p / 3, p % 3, q / 3, q % 3 };
        float c0 = 0.f, c1 = 0.f, c2 = 0.f, c3 = 0.f;
        for (int t = 0; t < 16; t++) {
            int j = 0, k = 0;
            float sgn = 1.f;
#pragma unroll
            for (int qq = 0; qq < 4; qq++) {
                int b = (t >> (3 - qq)) & 1;
                int jq, kq;
                if (mq[qq] == 0)      { jq = b; kq = b; }
                else if (mq[qq] == 1) { jq = b; kq = b; if (b) sgn = -sgn; }
                else                  { jq = b; kq = 1 - b; }
                j = (j << 1) | jq;
                k = (k << 1) | kq;
            }
            c0 += sgn * sM[0][j][k];
            c1 += sgn * sM[1][j][k];
            c2 += sgn * sM[2][j][k];
            c3 += sgn * sM[3][j][k];
        }
        g_C[h * 81 + m] = make_float4(c0 * 0.0625f, c1 * 0.0625f,
                                      c2 * 0.0625f, c3 * 0.0625f);
    }
}

// ---------------------------------------------------------------------------
// Phase-1 worker: heads H0..H0+3 (compile-time) for tokens tA and tB.
// All c_C indices are compile-time -> immediate-offset constant loads.
// ---------------------------------------------------------------------------
template <int H0>
__device__ __forceinline__ void phase1_4heads(
    const float4* __restrict__ xA4, const float4* __restrict__ xB4,
    float* __restrict__ sEv, int rowA, int rowB)
{
#pragma unroll
    for (int hh = 0; hh < 4; hh++) {
        const int h = H0 + hh;            // compile-time
        float4 aA = xA4[h];
        float4 aB = xB4[h];
        float cA0, sA0, cA1, sA1, cA2, sA2, cA3, sA3;
        float cB0, sB0, cB1, sB1, cB2, sB2, cB3, sB3;
        __sincosf(aA.x, &sA0, &cA0);
        __sincosf(aA.y, &sA1, &cA1);
        __sincosf(aA.z, &sA2, &cA2);
        __sincosf(aA.w, &sA3, &cA3);
        __sincosf(aB.x, &sB0, &cB0);
        __sincosf(aB.y, &sB1, &cB1);
        __sincosf(aB.z, &sB2, &cB2);
        __sincosf(aB.w, &sB3, &cB3);

        float uA[3] = { 1.f, cA0, sA0 }, vA[3] = { 1.f, cA1, sA1 };
        float uB[3] = { 1.f, cB0, sB0 }, vB[3] = { 1.f, cB1, sB1 };

        unsigned long long gA23d[9], gB23d[9];
        {
            float gA23[9] = { 1.f, cA3, sA3, cA2, cA2*cA3, cA2*sA3, sA2, sA2*cA3, sA2*sA3 };
            float gB23[9] = { 1.f, cB3, sB3, cB2, cB2*cB3, cB2*sB3, sB2, sB2*cB3, sB2*sB3 };
#pragma unroll
            for (int q = 0; q < 9; q++) {
                gA23d[q] = pk2(gA23[q], gA23[q]);
                gB23d[q] = pk2(gB23[q], gB23[q]);
            }
        }

        unsigned long long evA01 = 0ULL, evA23 = 0ULL;
        unsigned long long evB01 = 0ULL, evB23 = 0ULL;
#pragma unroll
        for (int p = 0; p < 9; p++) {
            unsigned long long tA01 = 0ULL, tA23 = 0ULL;
            unsigned long long tB01 = 0ULL, tB23 = 0ULL;
#pragma unroll
            for (int q = 0; q < 9; q++) {
                ulonglong2 cc = c_C[h * 81 + p * 9 + q];   // immediate offset
                fma2(tA01, cc.x, gA23d[q]);
                fma2(tA23, cc.y, gA23d[q]);
                fma2(tB01, cc.x, gB23d[q]);
                fma2(tB23, cc.y, gB23d[q]);
            }
            float gA = uA[p / 3] * vA[p % 3];
            float gB = uB[p / 3] * vB[p % 3];
            unsigned long long gpA = pk2(gA, gA);
            unsigned long long gpB = pk2(gB, gB);
            fma2(evA01, gpA, tA01);
            fma2(evA23, gpA, tA23);
            fma2(evB01, gpB, tB01);
            fma2(evB23, gpB, tB23);
        }

        float e0, e1, e2, e3;
        unpk2(e0, e1, evA01); unpk2(e2, e3, evA23);
        float* dA = &sEv[rowA * 33 + h * 4];
        dA[0] = e0; dA[1] = e1; dA[2] = e2; dA[3] = e3;
        unpk2(e0, e1, evB01); unpk2(e2, e3, evB23);
        float* dB = &sEv[rowB * 33 + h * 4];
        dB[0] = e0; dB[1] = e1; dB[2] = e2; dB[3] = e3;
    }
}

// ---------------------------------------------------------------------------
// Main: block = 128 threads, 128 tokens, grid = ntok/128 = 1024.
// Phase 1: thread = (2 tokens x 4 heads). Head-half chosen by (tid<64),
//          warp-uniform, heads compile-time inside each template branch.
//          Per-warp LDC.128 count = 324 (half of r13) at ~2x r7's warps.
// Phase 2: block GEMM out = ev @ Wt + b; thread = 4 tokens x 8 outputs.
// ---------------------------------------------------------------------------
__global__ __launch_bounds__(128, 5) void qmha_main(
    const float* __restrict__ x,
    const float* __restrict__ W,      // [32][32] row-major
    const float* __restrict__ bvec,   // [32]
    float* __restrict__ out,
    int ntok)
{
    __shared__ float sEv[128 * 33];
    __shared__ __align__(16) float sWt[32 * 32];      // sWt[k*32+j] = W[j*32+k]
    __shared__ float sb[32];

    int tid = threadIdx.x;
    for (int i = tid; i < 1024; i += 128) {
        int k = i >> 5, j = i & 31;
        sWt[k * 32 + j] = W[j * 32 + k];
    }
    if (tid < 32) sb[tid] = bvec[tid];

    int base = blockIdx.x * 128;
    int tl = tid & 63;                 // token lane 0..63
    int tA = base + tl;
    int tB = base + 64 + tl;
    const float4* xA4 = reinterpret_cast<const float4*>(
        x + (size_t)(tA < ntok ? tA : 0) * 32);
    const float4* xB4 = reinterpret_cast<const float4*>(
        x + (size_t)(tB < ntok ? tB : 0) * 32);

    // ---- Phase 1 ----
    if (tid < 64) phase1_4heads<0>(xA4, xB4, sEv, tl, 64 + tl);
    else          phase1_4heads<4>(xA4, xB4, sEv, tl, 64 + tl);

    __syncthreads();

    // ---- Phase 2: out[128][32] = ev[128][32] @ sWt[32][32] + b ----
    int jg = tid & 3;        // output group of 8: columns jg*8 .. jg*8+7
    int tg = tid >> 2;       // token sub-index (0..31); tokens tg + 32*m

    unsigned long long acc[4][4];
#pragma unroll
    for (int m = 0; m < 4; m++)
#pragma unroll
        for (int c = 0; c < 4; c++)
            acc[m][c] = pk2(sb[jg * 8 + 2 * c], sb[jg * 8 + 2 * c + 1]);

#pragma unroll
    for (int k = 0; k < 32; k++) {
        const ulonglong2* w2 =
            reinterpret_cast<const ulonglong2*>(sWt + k * 32 + jg * 8);
        ulonglong2 wa = w2[0];   // outputs jg*8+0..3
        ulonglong2 wb = w2[1];   // outputs jg*8+4..7
#pragma unroll
        for (int m = 0; m < 4; m++) {
            float e = sEv[(tg + 32 * m) * 33 + k];  // bank (tg+k)%32, bcast x4
            unsigned long long ed = pk2(e, e);
            fma2(acc[m][0], ed, wa.x);
            fma2(acc[m][1], ed, wa.y);
            fma2(acc[m][2], ed, wb.x);
            fma2(acc[m][3], ed, wb.y);
        }
    }

#pragma unroll
    for (int m = 0; m < 4; m++) {
        int to = base + tg + 32 * m;
        if (to < ntok) {
            float4* o = reinterpret_cast<float4*>(out + (size_t)to * 32 + jg * 8);
            float a0, a1, a2, a3;
            unpk2(a0, a1, acc[m][0]);
            unpk2(a2, a3, acc[m][1]);
            o[0] = make_float4(a0, a1, a2, a3);
            unpk2(a0, a1, acc[m][2]);
            unpk2(a2, a3, acc[m][3]);
            o[1] = make_float4(a0, a1, a2, a3);
        }
    }
}

extern "C" void kernel_launch(void* const* d_in, const int* in_sizes, int n_in,
                              void* d_out, int out_size) {
    const float* x      = (const float*)d_in[0];  // [B,S,32]
    const float* params = (const float*)d_in[1];  // [8,2,4,3]
    const float* W      = (const float*)d_in[2];  // [32,32]
    const float* b      = (const float*)d_in[3];  // [32]
    float* out = (float*)d_out;

    int ntok = in_sizes[0] / 32;

    build_all<<<NH, 128>>>(params);

    // D2D memcpy into the constant bank (proven capturable).
    void* gC_ptr = nullptr;
    void* cC_ptr = nullptr;
    cudaGetSymbolAddress(&gC_ptr, g_C);
    cudaGetSymbolAddress(&cC_ptr, c_C);
    cudaMemcpyAsync(cC_ptr, gC_ptr, sizeof(float4) * NH * 81,
                    cudaMemcpyDeviceToDevice, 0);

    int blocks = (ntok + 127) / 128;
    qmha_main<<<blocks, 128>>>(x, W, b, out, ntok);
}